// round 8
// baseline (speedup 1.0000x reference)
#include <cuda_runtime.h>

// LogLinearAttention — algebraic collapse (exact; rel_err=0 every round):
//   softmax over axis=1 then sum over axis=1 => attention columns sum to 1:
//     out[b] = sigmoid( xsum[b,:]·c + S*(br·Wl) + bl )
//   xsum[b,e] = sum_s x[b,s,e],  c[e] = sum_d Wl[d]*Wr[d,e].
//
// R7: k_c's ~4.8us proved to be fixed launch exposure (structure-invariant
// R4 vs R6). Remove it from the critical path: the x pass computes partial
// xsum vectors (needs no c) with the EXACT validated k_main load loop, and
// the c-partial blocks ride in the same grid. One-wave dot kernel + finisher.

#define BB 8
#define SS 2048
#define DD 512
#define DD4 (DD / 4)              // 128 float4 columns
#define JPB 37                    // row-range blocks per batch
#define NBLK (BB * JPB)           // 296 xsum blocks
#define VPB (2 * JPB)             // 74 partial vectors per batch (2 r0-phases)
#define CBLK_D 16                 // d-chunks for c partials
#define CBLK_E 8                  // e-chunk blocks for c partials
#define DCH (DD / CBLK_D)         // 32 d rows per chunk
#define ECH4 (DD4 / CBLK_E)       // 16 float4 cols per chunk
#define NCB (CBLK_D * CBLK_E)     // 128 c blocks
#define DPB 16                    // dot blocks per batch

__device__ float g_xp[NBLK * 2 * DD];   // partial xsum vectors (1.2 MB)
__device__ float g_cpart[CBLK_D * DD];  // c partials over d-chunks (32 KB)
__device__ float g_dots[BB * DPB];      // per-block partial dot scalars

// ── K1: 296 xsum blocks + 128 c blocks, one grid, fully independent ──
__global__ void __launch_bounds__(256) k_stream(
    const float* __restrict__ x,
    const float* __restrict__ Wr,
    const float* __restrict__ Wl)
{
    const int blk = blockIdx.x;
    const int tid = threadIdx.x;

    if (blk < NBLK) {
        // ── validated k_main load loop; only the accumulator/epilogue differ ──
        const int b   = blk / JPB;
        const int j   = blk % JPB;
        const int col = tid & (DD4 - 1);          // float4 column 0..127
        const int r0  = tid >> 7;                 // 0 or 1

        const int r_begin = (j * SS) / JPB;
        const int r_end   = ((j + 1) * SS) / JPB;
        const float4* xb  = reinterpret_cast<const float4*>(x + (size_t)b * SS * DD);

        float4 acc = make_float4(0.f, 0.f, 0.f, 0.f);
        int r = r_begin + r0;
#pragma unroll 4
        for (; r < r_end; r += 2) {               // continuous stream, MLP_p1 ~ 4
            float4 v = xb[(size_t)r * DD4 + col];
            acc.x += v.x; acc.y += v.y; acc.z += v.z; acc.w += v.w;
        }
        // vector id = blk*2 + r0  (contiguous per batch: b*74 + ...)
        reinterpret_cast<float4*>(g_xp)[((size_t)blk * 2 + r0) * DD4 + col] = acc;
    } else {
        // c partial: block (jd, je) covers d rows [jd*32,+32), f4 cols [je*16,+16)
        const int cb = blk - NBLK;
        const int jd = cb >> 3;                   // 0..15
        const int je = cb & 7;                    // 0..7
        const int td = tid >> 4;                  // d-subgroup 0..15 (2 rows each)
        const int tf = tid & 15;                  // float4 col in chunk

        const int e4 = je * ECH4 + tf;
        float4 acc = make_float4(0.f, 0.f, 0.f, 0.f);
#pragma unroll
        for (int k = 0; k < 2; ++k) {
            const int d = jd * DCH + td * 2 + k;
            const float wl = __ldg(&Wl[d]);
            const float4 w = reinterpret_cast<const float4*>(Wr)[(size_t)d * DD4 + e4];
            acc.x += wl * w.x; acc.y += wl * w.y; acc.z += wl * w.z; acc.w += wl * w.w;
        }

        __shared__ float4 s[16][ECH4];            // 4 KB
        s[td][tf] = acc;
        __syncthreads();
#pragma unroll
        for (int off = 8; off > 0; off >>= 1) {
            if (td < off) {
                float4 a = s[td][tf], b2 = s[td + off][tf];
                s[td][tf] = make_float4(a.x + b2.x, a.y + b2.y, a.z + b2.z, a.w + b2.w);
            }
            __syncthreads();
        }
        if (td == 0)
            reinterpret_cast<float4*>(g_cpart)[(size_t)jd * DD4 + e4] = s[0][tf];
    }
}

// ── K2: 128 one-wave blocks: fold xsum partials + fold c, dot → scalar ──
__global__ void __launch_bounds__(128) k_dot()
{
    const int b   = blockIdx.x / DPB;
    const int i   = blockIdx.x % DPB;
    const int tid = threadIdx.x;               // one float4 column each

    // strided fold over this batch's 74 partial vectors (L2-hot)
    float4 acc = make_float4(0.f, 0.f, 0.f, 0.f);
    const float4* pp = reinterpret_cast<const float4*>(g_xp) + (size_t)b * VPB * DD4 + tid;
    for (int p = i; p < VPB; p += DPB) {
        float4 v = pp[(size_t)p * DD4];
        acc.x += v.x; acc.y += v.y; acc.z += v.z; acc.w += v.w;
    }

    float4 c4 = make_float4(0.f, 0.f, 0.f, 0.f);
#pragma unroll
    for (int jd = 0; jd < CBLK_D; ++jd) {
        float4 v = reinterpret_cast<const float4*>(g_cpart)[(size_t)jd * DD4 + tid];
        c4.x += v.x; c4.y += v.y; c4.z += v.z; c4.w += v.w;
    }

    float val = acc.x * c4.x + acc.y * c4.y + acc.z * c4.z + acc.w * c4.w;
#pragma unroll
    for (int off = 16; off > 0; off >>= 1)
        val += __shfl_down_sync(0xffffffffu, val, off);
    __shared__ float warp_s[4];
    if ((tid & 31) == 0) warp_s[tid >> 5] = val;
    __syncthreads();
    if (tid == 0)
        g_dots[blockIdx.x] = warp_s[0] + warp_s[1] + warp_s[2] + warp_s[3];
}

// ── K3: fold 16 dot scalars per batch + bias term, sigmoid ──
__global__ void __launch_bounds__(128) k_final(
    const float* __restrict__ br,
    const float* __restrict__ Wl,
    const float* __restrict__ bl,
    float* __restrict__ out)
{
    const int tid = threadIdx.x;
    __shared__ float warp_s[4];
    __shared__ float s_bias;

    // bias dot br·Wl over 512 elems (float4 per thread)
    const float4 br4 = reinterpret_cast<const float4*>(br)[tid];
    const float4 wl4 = reinterpret_cast<const float4*>(Wl)[tid];
    float bv = br4.x * wl4.x + br4.y * wl4.y + br4.z * wl4.z + br4.w * wl4.w;
#pragma unroll
    for (int off = 16; off > 0; off >>= 1)
        bv += __shfl_down_sync(0xffffffffu, bv, off);
    if ((tid & 31) == 0) warp_s[tid >> 5] = bv;
    __syncthreads();
    if (tid == 0) s_bias = warp_s[0] + warp_s[1] + warp_s[2] + warp_s[3];
    __syncthreads();

    // fold 16 scalars per batch: tid -> (b = tid>>4, i = tid&15), warp-local
    float d = g_dots[tid];                     // BB*DPB = 128 scalars
#pragma unroll
    for (int off = 8; off > 0; off >>= 1)
        d += __shfl_down_sync(0xffffffffu, d, off, 16);
    if ((tid & 15) == 0) {
        const int b = tid >> 4;
        float z = d + (float)SS * s_bias + bl[0];
        out[b] = 1.0f / (1.0f + expf(-z));
    }
}

extern "C" void kernel_launch(void* const* d_in, const int* in_sizes, int n_in,
                              void* d_out, int out_size)
{
    // metadata order: x, Wq, bq, Wv, bv, Wr, br, Wl, bl
    const float* x  = (const float*)d_in[0];
    const float* Wr = (const float*)d_in[5];
    const float* br = (const float*)d_in[6];
    const float* Wl = (const float*)d_in[7];
    const float* bl = (const float*)d_in[8];
    float* out = (float*)d_out;

    k_stream<<<NBLK + NCB, 256>>>(x, Wr, Wl);
    k_dot<<<BB * DPB, 128>>>();
    k_final<<<1, 128>>>(br, Wl, bl, out);
}